// round 2
// baseline (speedup 1.0000x reference)
#include <cuda_runtime.h>
#include <math.h>

#define BN 16
#define DD 512
#define TT 2048
#define CC 20
#define KK 7
#define FF (CC*KK)
#define D4 (DD/4)
#define EPSV 1e-8f
#define BIGV 1e9f
#define THSIM 0.5f
#define THDIF 0.1f

// -------- scratch (static device globals; no runtime allocation) --------
__device__ float g_fgE[(size_t)BN*FF*DD];     // gathered fg embeddings [b][f][d]
__device__ float g_bgE[(size_t)BN*TT*DD];     // gathered bg embeddings (worst case T per batch)
__device__ float g_fg_nrm[BN*FF];
__device__ float g_bg_nrm[BN*TT];
__device__ int   g_fg_idx[BN*FF];
__device__ int   g_bg_idx[BN*TT];
__device__ int   g_bg_cnt[BN];
__device__ float g_minff[BN*FF];
__device__ float g_maxfb[BN*FF];
__device__ float g_minbb[BN*TT];
__device__ float g_maxbf[BN*TT];
__device__ float g_perbatch[BN];

// -------- helpers --------
__device__ __forceinline__ float dot_row(const float4* __restrict__ srow,
                                         const float* __restrict__ grow) {
    const float4* g4 = reinterpret_cast<const float4*>(grow);
    float a0 = 0.f, a1 = 0.f, a2 = 0.f, a3 = 0.f;
#pragma unroll 8
    for (int i = 0; i < D4; i++) {
        float4 a = srow[i];
        float4 x = g4[i];
        a0 += a.x * x.x; a1 += a.y * x.y; a2 += a.z * x.z; a3 += a.w * x.w;
    }
    return (a0 + a1) + (a2 + a3);
}

// -------- top-k: 7 sequential argmax reductions per (b,c) --------
__global__ void k_topk(const float* __restrict__ cas) {
    int c = blockIdx.x, b = blockIdx.y, tid = threadIdx.x;
    const float* row = cas + ((size_t)b * CC + c) * TT;
    __shared__ float sv[256];
    __shared__ int   si[256];
    __shared__ int   chosen[KK];
    for (int k = 0; k < KK; k++) {
        float bv = -INFINITY; int bi = 0;   // valid-index sentinel: never OOB
        for (int t = tid; t < TT; t += 256) {
            bool skip = false;
            for (int q = 0; q < k; q++) if (chosen[q] == t) skip = true;
            if (skip) continue;
            float v = row[t];
            if (v > bv || (v == bv && t < bi)) { bv = v; bi = t; }
        }
        sv[tid] = bv; si[tid] = bi;
        __syncthreads();
        for (int s = 128; s > 0; s >>= 1) {
            if (tid < s) {
                float ov = sv[tid + s]; int oi = si[tid + s];
                if (ov > sv[tid] || (ov == sv[tid] && oi < si[tid])) { sv[tid] = ov; si[tid] = oi; }
            }
            __syncthreads();
        }
        if (tid == 0) { chosen[k] = si[0]; g_fg_idx[b * FF + c * KK + k] = si[0]; }
        __syncthreads();
    }
}

// -------- deterministic ordered compaction of background indices --------
__global__ void k_compact(const int* __restrict__ click, const int* __restrict__ clsnum) {
    int b = blockIdx.x, tid = threadIdx.x;
    int cn = clsnum ? clsnum[0] : CC;
    __shared__ int woff[8];
    __shared__ int sbase;
    if (tid == 0) sbase = 0;
    __syncthreads();
    for (int chunk = 0; chunk < TT; chunk += 256) {
        int t = chunk + tid;
        int pred = (click[b * TT + t] == cn) ? 1 : 0;
        unsigned ball = __ballot_sync(0xffffffffu, pred);
        int w = tid >> 5, lane = tid & 31;
        if (lane == 0) woff[w] = __popc(ball);
        __syncthreads();
        if (tid == 0) {
            int s = sbase;
            for (int i = 0; i < 8; i++) { int cc = woff[i]; woff[i] = s; s += cc; }
            sbase = s;
        }
        __syncthreads();
        if (pred) {
            int pos = woff[w] + __popc(ball & ((1u << lane) - 1u));
            g_bg_idx[b * TT + pos] = t;
        }
        __syncthreads();
    }
    if (tid == 0) g_bg_cnt[b] = sbase;
}

// -------- gathers: strided column reads, MLP-batched; norms on the fly --------
__device__ __forceinline__ void gather_col(const float* __restrict__ base,
                                           float* __restrict__ dst,
                                           float* __restrict__ nrm_out,
                                           int tid) {
    float acc = 0.f;
    // 512 elems / 128 threads = 4 per thread; issue all 4 loads before any store
    float v0 = base[(size_t)(tid      ) * TT];
    float v1 = base[(size_t)(tid + 128) * TT];
    float v2 = base[(size_t)(tid + 256) * TT];
    float v3 = base[(size_t)(tid + 384) * TT];
    dst[tid      ] = v0;
    dst[tid + 128] = v1;
    dst[tid + 256] = v2;
    dst[tid + 384] = v3;
    acc = v0 * v0 + v1 * v1 + v2 * v2 + v3 * v3;
    __shared__ float red[128];
    red[tid] = acc; __syncthreads();
    for (int s = 64; s > 0; s >>= 1) { if (tid < s) red[tid] += red[tid + s]; __syncthreads(); }
    if (tid == 0) *nrm_out = sqrtf(red[0]);
}

__global__ void k_gather_fg(const float* __restrict__ emb) {
    int f = blockIdx.x, b = blockIdx.y, tid = threadIdx.x;
    int col = g_fg_idx[b * FF + f];
    gather_col(emb + (size_t)b * DD * TT + col,
               g_fgE + ((size_t)b * FF + f) * DD,
               &g_fg_nrm[b * FF + f], tid);
}

__global__ void k_gather_bg(const float* __restrict__ emb) {
    int i = blockIdx.x, b = blockIdx.y, tid = threadIdx.x;
    if (i >= g_bg_cnt[b]) return;
    int col = g_bg_idx[b * TT + i];
    gather_col(emb + (size_t)b * DD * TT + col,
               g_bgE + ((size_t)b * TT + i) * DD,
               &g_bg_nrm[b * TT + i], tid);
}

// -------- fg-to-fg: min cosine over masked fg columns --------
__global__ void k_ff(const int* __restrict__ label) {
    int f = blockIdx.x, b = blockIdx.y, tid = threadIdx.x;
    __shared__ float4 srow[D4];
    const float* rowp = g_fgE + ((size_t)b * FF + f) * DD;
    srow[tid] = reinterpret_cast<const float4*>(rowp)[tid];
    __syncthreads();
    float nf = g_fg_nrm[b * FF + f];
    float mn = BIGV;
    for (int g = tid; g < FF; g += 128) {
        if (label[b * CC + g / KK] == 1) {
            float d = dot_row(srow, g_fgE + ((size_t)b * FF + g) * DD);
            float cs = d / fmaxf(nf * g_fg_nrm[b * FF + g], EPSV);
            mn = fminf(mn, cs);
        }
    }
    __shared__ float red[128];
    red[tid] = mn; __syncthreads();
    for (int s = 64; s > 0; s >>= 1) { if (tid < s) red[tid] = fminf(red[tid], red[tid + s]); __syncthreads(); }
    if (tid == 0) g_minff[b * FF + f] = red[0];
}

// -------- bg-to-bg: min cosine over bg columns, rows in bg only --------
__global__ void k_bb() {
    int i = blockIdx.x, b = blockIdx.y, tid = threadIdx.x;
    int cnt = g_bg_cnt[b];
    if (i >= cnt) return;
    __shared__ float4 srow[D4];
    const float* rowp = g_bgE + ((size_t)b * TT + i) * DD;
    srow[tid] = reinterpret_cast<const float4*>(rowp)[tid];
    __syncthreads();
    float ni = g_bg_nrm[b * TT + i];
    float mn = BIGV;
    for (int j = tid; j < cnt; j += 128) {
        float d = dot_row(srow, g_bgE + ((size_t)b * TT + j) * DD);
        float cs = d / fmaxf(ni * g_bg_nrm[b * TT + j], EPSV);
        mn = fminf(mn, cs);
    }
    __shared__ float red[128];
    red[tid] = mn; __syncthreads();
    for (int s = 64; s > 0; s >>= 1) { if (tid < s) red[tid] = fminf(red[tid], red[tid + s]); __syncthreads(); }
    if (tid == 0) g_minbb[b * TT + i] = red[0];
}

// -------- fg-to-bg row max (over bg columns) --------
__global__ void k_fb() {
    int f = blockIdx.x, b = blockIdx.y, tid = threadIdx.x;
    int cnt = g_bg_cnt[b];
    __shared__ float4 srow[D4];
    const float* rowp = g_fgE + ((size_t)b * FF + f) * DD;
    srow[tid] = reinterpret_cast<const float4*>(rowp)[tid];
    __syncthreads();
    float nf = g_fg_nrm[b * FF + f];
    float mx = -BIGV;
    for (int j = tid; j < cnt; j += 128) {
        float d = dot_row(srow, g_bgE + ((size_t)b * TT + j) * DD);
        float cs = d / fmaxf(nf * g_bg_nrm[b * TT + j], EPSV);
        mx = fmaxf(mx, cs);
    }
    __shared__ float red[128];
    red[tid] = mx; __syncthreads();
    for (int s = 64; s > 0; s >>= 1) { if (tid < s) red[tid] = fmaxf(red[tid], red[tid + s]); __syncthreads(); }
    if (tid == 0) g_maxfb[b * FF + f] = red[0];
}

// -------- bg-to-fg column max (over masked fg rows) --------
__global__ void k_bf(const int* __restrict__ label) {
    int j = blockIdx.x, b = blockIdx.y, tid = threadIdx.x;
    int cnt = g_bg_cnt[b];
    if (j >= cnt) return;
    __shared__ float4 srow[D4];
    const float* rowp = g_bgE + ((size_t)b * TT + j) * DD;
    srow[tid] = reinterpret_cast<const float4*>(rowp)[tid];
    __syncthreads();
    float nj = g_bg_nrm[b * TT + j];
    float mx = -BIGV;
    for (int f = tid; f < FF; f += 128) {
        if (label[b * CC + f / KK] == 1) {
            float d = dot_row(srow, g_fgE + ((size_t)b * FF + f) * DD);
            float cs = d / fmaxf(g_fg_nrm[b * FF + f] * nj, EPSV);
            mx = fmaxf(mx, cs);
        }
    }
    __shared__ float red[128];
    red[tid] = mx; __syncthreads();
    for (int s = 64; s > 0; s >>= 1) { if (tid < s) red[tid] = fmaxf(red[tid], red[tid + s]); __syncthreads(); }
    if (tid == 0) g_maxbf[b * TT + j] = red[0];
}

// -------- per-batch masked means --------
__global__ void k_batch(const int* __restrict__ label) {
    int b = blockIdx.x, tid = threadIdx.x;
    int cnt = g_bg_cnt[b];
    float sm = 0.f, sff = 0.f, sfb = 0.f, sbb = 0.f, sbf = 0.f;
    for (int f = tid; f < FF; f += 256) {
        float m = (label[b * CC + f / KK] == 1) ? 1.f : 0.f;
        sm  += m;
        sff += m * fmaxf(THSIM - g_minff[b * FF + f], 0.f);
        sfb += m * fmaxf(g_maxfb[b * FF + f] - THDIF, 0.f);
    }
    for (int i = tid; i < cnt; i += 256) {
        sbb += fmaxf(THSIM - g_minbb[b * TT + i], 0.f);
        sbf += fmaxf(g_maxbf[b * TT + i] - THDIF, 0.f);
    }
    __shared__ float r0[256], r1[256], r2[256], r3[256], r4[256];
    r0[tid] = sm; r1[tid] = sff; r2[tid] = sfb; r3[tid] = sbb; r4[tid] = sbf;
    __syncthreads();
    for (int s = 128; s > 0; s >>= 1) {
        if (tid < s) {
            r0[tid] += r0[tid + s]; r1[tid] += r1[tid + s]; r2[tid] += r2[tid + s];
            r3[tid] += r3[tid + s]; r4[tid] += r4[tid + s];
        }
        __syncthreads();
    }
    if (tid == 0) {
        float denf = fmaxf(r0[0], 1.f);
        float denb = fmaxf((float)cnt, 1.f);
        float loss = r1[0] / denf + r2[0] / denf + r3[0] / denb + r4[0] / denb;
        g_perbatch[b] = (cnt > 0) ? loss : 0.f;
    }
}

__global__ void k_final(float* __restrict__ out) {
    if (threadIdx.x == 0) {
        float s = 0.f; int c = 0;
        for (int b = 0; b < BN; b++) { s += g_perbatch[b]; if (g_bg_cnt[b] > 0) c++; }
        out[0] = s / fmaxf((float)c, 1.f);
    }
}

extern "C" void kernel_launch(void* const* d_in, const int* in_sizes, int n_in,
                              void* d_out, int out_size) {
    const float* emb    = (const float*)d_in[0];
    const float* cas    = (const float*)d_in[1];
    const int*   click  = (const int*)d_in[2];
    const int*   label  = (const int*)d_in[3];
    const int*   clsnum = (n_in >= 5) ? (const int*)d_in[4] : nullptr;

    k_topk   <<<dim3(CC, BN), 256>>>(cas);
    k_compact<<<BN, 256>>>(click, clsnum);
    k_gather_fg<<<dim3(FF, BN), 128>>>(emb);
    k_gather_bg<<<dim3(TT, BN), 128>>>(emb);
    k_ff<<<dim3(FF, BN), 128>>>(label);
    k_bb<<<dim3(TT, BN), 128>>>();
    k_fb<<<dim3(FF, BN), 128>>>();
    k_bf<<<dim3(TT, BN), 128>>>(label);
    k_batch<<<BN, 256>>>(label);
    k_final<<<1, 32>>>((float*)d_out);
}

// round 3
// speedup vs baseline: 3.1138x; 3.1138x over previous
#include <cuda_runtime.h>
#include <math.h>

#define BN 16
#define DD 512
#define TT 2048
#define CC 20
#define KK 7
#define FF (CC*KK)            // 140
#define PT 2208               // padded point capacity per batch: 69*32 >= FF+TT
#define MAXTIL 69             // ceil(PT/32)
#define EPSV 1e-8f
#define BIGV 1e9f
#define THSIM 0.5f
#define THDIF 0.1f
#define SIM_BLOCKS 1024

// -------- scratch (static device globals; no runtime allocation) --------
__device__ float    g_E[(size_t)BN*PT*DD];    // unified gathered points [b][p][d]; p<FF: fg, p>=FF: bg
__device__ float    g_nrm[BN*PT];
__device__ int      g_fg_idx[BN*FF];
__device__ int      g_bg_idx[BN*TT];
__device__ int      g_bg_cnt[BN];
__device__ unsigned g_redA[BN*PT];            // fg row: min_ff ; bg row: max_bf   (monotonic-uint encoded)
__device__ unsigned g_redB[BN*PT];            // fg row: max_fb ; bg row: min_bb
__device__ int      g_Nb[BN];
__device__ int      g_tiles[BN];
__device__ int      g_item_off[BN+1];
__device__ float    g_perbatch[BN];

// monotonic float<->uint encoding: order-preserving, exact
__device__ __forceinline__ unsigned fenc(float f) {
    unsigned u = __float_as_uint(f);
    return (u & 0x80000000u) ? ~u : (u | 0x80000000u);
}
__device__ __forceinline__ float fdec(unsigned x) {
    return (x & 0x80000000u) ? __uint_as_float(x ^ 0x80000000u) : __uint_as_float(~x);
}

// -------- top-k: 7 sequential argmax reductions per (b,c) --------
__global__ void k_topk(const float* __restrict__ cas) {
    int c = blockIdx.x, b = blockIdx.y, tid = threadIdx.x;
    const float* row = cas + ((size_t)b * CC + c) * TT;
    __shared__ float sv[256];
    __shared__ int   si[256];
    __shared__ int   chosen[KK];
    for (int k = 0; k < KK; k++) {
        float bv = -INFINITY; int bi = 0;
        for (int t = tid; t < TT; t += 256) {
            bool skip = false;
            for (int q = 0; q < k; q++) if (chosen[q] == t) skip = true;
            if (skip) continue;
            float v = row[t];
            if (v > bv || (v == bv && t < bi)) { bv = v; bi = t; }
        }
        sv[tid] = bv; si[tid] = bi;
        __syncthreads();
        for (int s = 128; s > 0; s >>= 1) {
            if (tid < s) {
                float ov = sv[tid + s]; int oi = si[tid + s];
                if (ov > sv[tid] || (ov == sv[tid] && oi < si[tid])) { sv[tid] = ov; si[tid] = oi; }
            }
            __syncthreads();
        }
        if (tid == 0) { chosen[k] = si[0]; g_fg_idx[b * FF + c * KK + k] = si[0]; }
        __syncthreads();
    }
}

// -------- bg compaction (deterministic order) + reduction-sentinel init --------
__global__ void k_compact(const int* __restrict__ click, const int* __restrict__ clsnum) {
    int b = blockIdx.x, tid = threadIdx.x;
    int cn = clsnum ? clsnum[0] : CC;
    // init atomic reduction buffers
    unsigned encBig = fenc(BIGV), encNeg = fenc(-BIGV);
    for (int p = tid; p < PT; p += 256) {
        bool fg = (p < FF);
        g_redA[b * PT + p] = fg ? encBig : encNeg;  // fg: min identity ; bg: max identity
        g_redB[b * PT + p] = fg ? encNeg : encBig;  // fg: max identity ; bg: min identity
    }
    __shared__ int woff[8];
    __shared__ int sbase;
    if (tid == 0) sbase = 0;
    __syncthreads();
    for (int chunk = 0; chunk < TT; chunk += 256) {
        int t = chunk + tid;
        int pred = (click[b * TT + t] == cn) ? 1 : 0;
        unsigned ball = __ballot_sync(0xffffffffu, pred);
        int w = tid >> 5, lane = tid & 31;
        if (lane == 0) woff[w] = __popc(ball);
        __syncthreads();
        if (tid == 0) {
            int s = sbase;
            for (int i = 0; i < 8; i++) { int cc = woff[i]; woff[i] = s; s += cc; }
            sbase = s;
        }
        __syncthreads();
        if (pred) {
            int pos = woff[w] + __popc(ball & ((1u << lane) - 1u));
            g_bg_idx[b * TT + pos] = t;
        }
        __syncthreads();
    }
    if (tid == 0) g_bg_cnt[b] = sbase;
}

// -------- plan: per-batch point counts, tile counts, work-item prefix --------
__global__ void k_plan() {
    if (threadIdx.x == 0) {
        int off = 0;
        for (int b = 0; b < BN; b++) {
            int N = FF + g_bg_cnt[b];
            int tiles = (N + 31) / 32;
            g_Nb[b] = N;
            g_tiles[b] = tiles;
            g_item_off[b] = off;
            off += tiles * tiles;
        }
        g_item_off[BN] = off;
    }
}

// -------- unified gather: one warp per point column, MLP=16 --------
__global__ void k_gather(const float* __restrict__ emb) {
    int b = blockIdx.y;
    int slot = blockIdx.x * 8 + (threadIdx.x >> 5);
    int lane = threadIdx.x & 31;
    int col;
    if (slot < FF) {
        col = g_fg_idx[b * FF + slot];
    } else {
        int i = slot - FF;
        if (i >= g_bg_cnt[b]) return;
        col = g_bg_idx[b * TT + i];
    }
    const float* base = emb + (size_t)b * DD * TT + col + (size_t)lane * TT;
    float* dst = g_E + ((size_t)b * PT + slot) * DD;
    float v[16];
#pragma unroll
    for (int i = 0; i < 16; i++) v[i] = base[(size_t)i * 32 * TT];
    float ss = 0.f;
#pragma unroll
    for (int i = 0; i < 16; i++) { dst[lane + 32 * i] = v[i]; ss += v[i] * v[i]; }
#pragma unroll
    for (int m = 16; m > 0; m >>= 1) ss += __shfl_xor_sync(0xffffffffu, ss, m);
    if (lane == 0) g_nrm[b * PT + slot] = sqrtf(ss);
}

// -------- fused tiled similarity: 32x32 tiles of E·E^T, routed min/max --------
__global__ void __launch_bounds__(256) k_sim(const int* __restrict__ label) {
    __shared__ float As[64][32];   // [dk][row]
    __shared__ float Bs[64][32];   // [dk][col]
    __shared__ int   smLab[CC];

    int tid = threadIdx.x;
    int tx = tid & 15;             // 2-col group
    int ty = tid >> 4;             // 2-row group
    int lr = tid & 31;             // load: row/col within tile
    int ldk = (tid >> 5) * 8;      // load: dk offset for this warp

    int total = g_item_off[BN];
    for (int item = blockIdx.x; item < total; item += SIM_BLOCKS) {
        // decode (b, row-tile, col-tile)
        int b = 0;
        while (b < BN - 1 && item >= g_item_off[b + 1]) b++;
        int local = item - g_item_off[b];
        int tiles = g_tiles[b];
        int rt = local / tiles, ct = local - rt * tiles;
        int Nb = g_Nb[b];
        int rowbase = rt * 32, colbase = ct * 32;

        if (tid < CC) smLab[tid] = label[b * CC + tid];
        __syncthreads();

        const float* Eb = g_E + (size_t)b * PT * DD;
        const float* rowp = Eb + (size_t)(rowbase + lr) * DD + ldk;
        const float* colp = Eb + (size_t)(colbase + lr) * DD + ldk;

        float a00 = 0.f, a01 = 0.f, a10 = 0.f, a11 = 0.f;
#pragma unroll 1
        for (int d0 = 0; d0 < DD; d0 += 64) {
            float4 r0 = *(const float4*)(rowp + d0);
            float4 r1 = *(const float4*)(rowp + d0 + 4);
            float4 c0 = *(const float4*)(colp + d0);
            float4 c1 = *(const float4*)(colp + d0 + 4);
            As[ldk + 0][lr] = r0.x; As[ldk + 1][lr] = r0.y; As[ldk + 2][lr] = r0.z; As[ldk + 3][lr] = r0.w;
            As[ldk + 4][lr] = r1.x; As[ldk + 5][lr] = r1.y; As[ldk + 6][lr] = r1.z; As[ldk + 7][lr] = r1.w;
            Bs[ldk + 0][lr] = c0.x; Bs[ldk + 1][lr] = c0.y; Bs[ldk + 2][lr] = c0.z; Bs[ldk + 3][lr] = c0.w;
            Bs[ldk + 4][lr] = c1.x; Bs[ldk + 5][lr] = c1.y; Bs[ldk + 6][lr] = c1.z; Bs[ldk + 7][lr] = c1.w;
            __syncthreads();
#pragma unroll
            for (int dk = 0; dk < 64; dk++) {
                float2 a = *(const float2*)&As[dk][ty * 2];
                float2 c = *(const float2*)&Bs[dk][tx * 2];
                a00 += a.x * c.x; a01 += a.x * c.y;
                a10 += a.y * c.x; a11 += a.y * c.y;
            }
            __syncthreads();
        }

        // epilogue: normalize + route into per-row reductions
        int c0i = colbase + 2 * tx, c1i = c0i + 1;
        bool c0bg = (c0i >= FF), c1bg = (c1i >= FF);
        bool c0ok = (c0i < Nb), c1ok = (c1i < Nb);
        bool c0m = c0ok && !c0bg && (smLab[c0i / KK] == 1);
        bool c1m = c1ok && !c1bg && (smLab[c1i / KK] == 1);
        float nc0 = g_nrm[b * PT + c0i], nc1 = g_nrm[b * PT + c1i];

#pragma unroll
        for (int rr = 0; rr < 2; rr++) {
            int ri = rowbase + 2 * ty + rr;
            bool rvalid = ri < Nb;
            bool rowfg = ri < FF;
            float nr = g_nrm[b * PT + ri];
            float s0 = (rr == 0 ? a00 : a10);
            float s1 = (rr == 0 ? a01 : a11);
            float cs0 = s0 / fmaxf(nr * nc0, EPSV);
            float cs1 = s1 / fmaxf(nr * nc1, EPSV);
            // A: over masked fg cols (row fg -> min, row bg -> max)
            // B: over bg cols        (row fg -> max, row bg -> min)
            float vA = rowfg ? BIGV : -BIGV;
            float vB = rowfg ? -BIGV : BIGV;
            if (c0m)            vA = rowfg ? fminf(vA, cs0) : fmaxf(vA, cs0);
            if (c1m)            vA = rowfg ? fminf(vA, cs1) : fmaxf(vA, cs1);
            if (c0ok && c0bg)   vB = rowfg ? fmaxf(vB, cs0) : fminf(vB, cs0);
            if (c1ok && c1bg)   vB = rowfg ? fmaxf(vB, cs1) : fminf(vB, cs1);
#pragma unroll
            for (int m = 8; m > 0; m >>= 1) {
                float oA = __shfl_xor_sync(0xffffffffu, vA, m);
                float oB = __shfl_xor_sync(0xffffffffu, vB, m);
                vA = rowfg ? fminf(vA, oA) : fmaxf(vA, oA);
                vB = rowfg ? fmaxf(vB, oB) : fminf(vB, oB);
            }
            if (tx == 0 && rvalid) {
                unsigned eA = fenc(vA), eB = fenc(vB);
                if (rowfg) { atomicMin(&g_redA[b * PT + ri], eA); atomicMax(&g_redB[b * PT + ri], eB); }
                else       { atomicMax(&g_redA[b * PT + ri], eA); atomicMin(&g_redB[b * PT + ri], eB); }
            }
        }
        __syncthreads();   // protect smLab/As/Bs before next item
    }
}

// -------- per-batch masked means --------
__global__ void k_batch(const int* __restrict__ label) {
    int b = blockIdx.x, tid = threadIdx.x;
    int cnt = g_bg_cnt[b];
    float sm = 0.f, sff = 0.f, sfb = 0.f, sbb = 0.f, sbf = 0.f;
    for (int f = tid; f < FF; f += 256) {
        float m = (label[b * CC + f / KK] == 1) ? 1.f : 0.f;
        float minff = fdec(g_redA[b * PT + f]);
        float maxfb = fdec(g_redB[b * PT + f]);
        sm  += m;
        sff += m * fmaxf(THSIM - minff, 0.f);
        sfb += m * fmaxf(maxfb - THDIF, 0.f);
    }
    for (int i = tid; i < cnt; i += 256) {
        float maxbf = fdec(g_redA[b * PT + FF + i]);
        float minbb = fdec(g_redB[b * PT + FF + i]);
        sbb += fmaxf(THSIM - minbb, 0.f);
        sbf += fmaxf(maxbf - THDIF, 0.f);
    }
    __shared__ float r0[256], r1[256], r2[256], r3[256], r4[256];
    r0[tid] = sm; r1[tid] = sff; r2[tid] = sfb; r3[tid] = sbb; r4[tid] = sbf;
    __syncthreads();
    for (int s = 128; s > 0; s >>= 1) {
        if (tid < s) {
            r0[tid] += r0[tid + s]; r1[tid] += r1[tid + s]; r2[tid] += r2[tid + s];
            r3[tid] += r3[tid + s]; r4[tid] += r4[tid + s];
        }
        __syncthreads();
    }
    if (tid == 0) {
        float denf = fmaxf(r0[0], 1.f);
        float denb = fmaxf((float)cnt, 1.f);
        float loss = r1[0] / denf + r2[0] / denf + r3[0] / denb + r4[0] / denb;
        g_perbatch[b] = (cnt > 0) ? loss : 0.f;
    }
}

__global__ void k_final(float* __restrict__ out) {
    if (threadIdx.x == 0) {
        float s = 0.f; int c = 0;
        for (int b = 0; b < BN; b++) { s += g_perbatch[b]; if (g_bg_cnt[b] > 0) c++; }
        out[0] = s / fmaxf((float)c, 1.f);
    }
}

extern "C" void kernel_launch(void* const* d_in, const int* in_sizes, int n_in,
                              void* d_out, int out_size) {
    const float* emb    = (const float*)d_in[0];
    const float* cas    = (const float*)d_in[1];
    const int*   click  = (const int*)d_in[2];
    const int*   label  = (const int*)d_in[3];
    const int*   clsnum = (n_in >= 5) ? (const int*)d_in[4] : nullptr;

    k_topk   <<<dim3(CC, BN), 256>>>(cas);
    k_compact<<<BN, 256>>>(click, clsnum);
    k_plan   <<<1, 32>>>();
    k_gather <<<dim3(PT / 8, BN), 256>>>(emb);
    k_sim    <<<SIM_BLOCKS, 256>>>(label);
    k_batch  <<<BN, 256>>>(label);
    k_final  <<<1, 32>>>((float*)d_out);
}

// round 4
// speedup vs baseline: 3.9476x; 1.2678x over previous
#include <cuda_runtime.h>
#include <math.h>

#define BN 16
#define DD 512
#define TT 2048
#define CC 20
#define KK 7
#define FF (CC*KK)            // 140
#define PT 2048               // unique points live in t-space -> <= T
#define TS 64                 // similarity tile
#define DKC 32                // k-chunk
#define EPSV 1e-8f
#define BIGV 1e9f
#define THSIM 0.5f
#define THDIF 0.1f
#define SIM_BLOCKS 512

// -------- scratch (static device globals; no runtime allocation) --------
__device__ float    g_Et[(size_t)BN*DD*PT];   // transposed gathered points [b][d][p]
__device__ float    g_nrm[BN*PT];
__device__ int      g_fg_idx[BN*FF];
__device__ int      g_slotmap[BN*TT];         // t -> slot or -1
__device__ int      g_sw[BN*PT];              // per-slot fg multiplicity weight
__device__ unsigned char g_sfg[BN*PT];        // slot is masked-fg point
__device__ unsigned char g_sbg[BN*PT];        // slot is bg point
__device__ int      g_Nb[BN];
__device__ int      g_bgcnt[BN];
__device__ int      g_sumw[BN];
__device__ int      g_tiles[BN];
__device__ int      g_item_off[BN+1];
__device__ unsigned g_minff[BN*PT];
__device__ unsigned g_maxfb[BN*PT];
__device__ unsigned g_minbb[BN*PT];
__device__ unsigned g_maxbf[BN*PT];
__device__ float    g_perbatch[BN];

// monotonic float<->uint encoding: order-preserving, exact
__device__ __forceinline__ unsigned fenc(float f) {
    unsigned u = __float_as_uint(f);
    return (u & 0x80000000u) ? ~u : (u | 0x80000000u);
}
__device__ __forceinline__ float fdec(unsigned x) {
    return (x & 0x80000000u) ? __uint_as_float(x ^ 0x80000000u) : __uint_as_float(~x);
}

// -------- top-k: 7 sequential argmax reductions per (b,c) --------
__global__ void k_topk(const float* __restrict__ cas) {
    int c = blockIdx.x, b = blockIdx.y, tid = threadIdx.x;
    const float* row = cas + ((size_t)b * CC + c) * TT;
    __shared__ float sv[256];
    __shared__ int   si[256];
    __shared__ int   chosen[KK];
    for (int k = 0; k < KK; k++) {
        float bv = -INFINITY; int bi = 0;
        for (int t = tid; t < TT; t += 256) {
            bool skip = false;
            for (int q = 0; q < k; q++) if (chosen[q] == t) skip = true;
            if (skip) continue;
            float v = row[t];
            if (v > bv || (v == bv && t < bi)) { bv = v; bi = t; }
        }
        sv[tid] = bv; si[tid] = bi;
        __syncthreads();
        for (int s = 128; s > 0; s >>= 1) {
            if (tid < s) {
                float ov = sv[tid + s]; int oi = si[tid + s];
                if (ov > sv[tid] || (ov == sv[tid] && oi < si[tid])) { sv[tid] = ov; si[tid] = oi; }
            }
            __syncthreads();
        }
        if (tid == 0) { chosen[k] = si[0]; g_fg_idx[b * FF + c * KK + k] = si[0]; }
        __syncthreads();
    }
}

// -------- prep: unique-point slots, flags, weights, reduction init --------
__global__ void k_prep(const int* __restrict__ click, const int* __restrict__ label,
                       const int* __restrict__ clsnum) {
    int b = blockIdx.x, tid = threadIdx.x;
    int cn = clsnum ? clsnum[0] : CC;
    __shared__ int w[TT];
    __shared__ int woff[8];
    __shared__ int sbase, sbg;
    for (int t = tid; t < TT; t += 256) w[t] = 0;
    unsigned encBig = fenc(BIGV), encNeg = fenc(-BIGV);
    for (int p = tid; p < PT; p += 256) {
        g_minff[b * PT + p] = encBig;
        g_maxfb[b * PT + p] = encNeg;
        g_minbb[b * PT + p] = encBig;
        g_maxbf[b * PT + p] = encNeg;
    }
    if (tid == 0) { sbase = 0; sbg = 0; }
    __syncthreads();
    for (int i = tid; i < FF; i += 256) {
        int c = i / KK;
        if (label[b * CC + c] == 1) atomicAdd(&w[g_fg_idx[b * FF + i]], 1);
    }
    __syncthreads();
    for (int chunk = 0; chunk < TT; chunk += 256) {
        int t = chunk + tid;
        int bg  = (click[b * TT + t] == cn) ? 1 : 0;
        int wt  = w[t];
        int sel = (bg || wt > 0) ? 1 : 0;
        unsigned ball = __ballot_sync(0xffffffffu, sel);
        unsigned ballbg = __ballot_sync(0xffffffffu, bg);
        int wi = tid >> 5, lane = tid & 31;
        if (lane == 0) { woff[wi] = __popc(ball); atomicAdd(&sbg, __popc(ballbg)); }
        __syncthreads();
        if (tid == 0) {
            int s = sbase;
            for (int i = 0; i < 8; i++) { int cc2 = woff[i]; woff[i] = s; s += cc2; }
            sbase = s;
        }
        __syncthreads();
        if (sel) {
            int pos = woff[wi] + __popc(ball & ((1u << lane) - 1u));
            g_slotmap[b * TT + t] = pos;
            g_sw[b * PT + pos] = wt;
            g_sfg[b * PT + pos] = (wt > 0) ? 1 : 0;
            g_sbg[b * PT + pos] = (unsigned char)bg;
        } else {
            g_slotmap[b * TT + t] = -1;
        }
        __syncthreads();
    }
    if (tid == 0) {
        int numpos = 0;
        for (int c = 0; c < CC; c++) numpos += (label[b * CC + c] == 1) ? 1 : 0;
        g_sumw[b]  = KK * numpos;
        g_bgcnt[b] = sbg;
        g_Nb[b]    = sbase;
        g_tiles[b] = (sbase + TS - 1) / TS;
    }
}

__global__ void k_plan() {
    if (threadIdx.x == 0) {
        int off = 0;
        for (int b = 0; b < BN; b++) {
            int t = g_tiles[b];
            g_item_off[b] = off;
            off += t * (t + 1) / 2;
        }
        g_item_off[BN] = off;
    }
}

// -------- transpose-gather: stream emb coalesced, scatter to Et[b][d][slot] --------
__global__ void k_gatherT(const float* __restrict__ emb) {
    int b = blockIdx.y, tid = threadIdx.x;
    int d0 = blockIdx.x * 32;
    __shared__ int smap[TT];
    for (int t = tid; t < TT; t += 256) smap[t] = g_slotmap[b * TT + t];
    __syncthreads();
    for (int dd = 0; dd < 32; dd++) {
        int d = d0 + dd;
        const float* src = emb + ((size_t)b * DD + d) * TT;
        float* dstrow = g_Et + ((size_t)b * DD + d) * PT;
        for (int t = tid; t < TT; t += 256) {
            float v = src[t];
            int s = smap[t];
            if (s >= 0) dstrow[s] = v;
        }
    }
}

// -------- per-slot norms: coalesced column-walk of Et --------
__global__ void k_norm() {
    int b = blockIdx.y;
    int p = blockIdx.x * 256 + threadIdx.x;
    if (p >= g_Nb[b]) return;
    const float* base = g_Et + (size_t)b * DD * PT + p;
    float s = 0.f;
#pragma unroll 8
    for (int d = 0; d < DD; d++) {
        float v = base[(size_t)d * PT];
        s += v * v;
    }
    g_nrm[b * PT + p] = sqrtf(s);
}

// -------- routing: per-row min/max over typed columns, atomic-merged --------
__device__ __forceinline__ void route_tile(const float acc[4][4], int b,
                                           int rowb, int colb, int Nb,
                                           int tx, int ty) {
    float nc[4]; int cfg[4], cbg[4];
#pragma unroll
    for (int j = 0; j < 4; j++) {
        int c = colb + 4 * tx + j;
        bool cok = (c < Nb);
        nc[j]  = g_nrm[b * PT + c];
        cfg[j] = cok && g_sfg[b * PT + c];
        cbg[j] = cok && g_sbg[b * PT + c];
    }
#pragma unroll
    for (int i = 0; i < 4; i++) {
        int ri = rowb + 4 * ty + i;
        float nr = g_nrm[b * PT + ri];
        float vFF = BIGV, vBF = -BIGV, vFB = -BIGV, vBB = BIGV;
#pragma unroll
        for (int j = 0; j < 4; j++) {
            float cs = acc[i][j] / fmaxf(nr * nc[j], EPSV);
            if (cfg[j]) { vFF = fminf(vFF, cs); vBF = fmaxf(vBF, cs); }
            if (cbg[j]) { vFB = fmaxf(vFB, cs); vBB = fminf(vBB, cs); }
        }
#pragma unroll
        for (int m = 8; m > 0; m >>= 1) {
            vFF = fminf(vFF, __shfl_xor_sync(0xffffffffu, vFF, m));
            vBF = fmaxf(vBF, __shfl_xor_sync(0xffffffffu, vBF, m));
            vFB = fmaxf(vFB, __shfl_xor_sync(0xffffffffu, vFB, m));
            vBB = fminf(vBB, __shfl_xor_sync(0xffffffffu, vBB, m));
        }
        if (tx == 0 && ri < Nb) {
            if (g_sfg[b * PT + ri]) {
                atomicMin(&g_minff[b * PT + ri], fenc(vFF));
                atomicMax(&g_maxfb[b * PT + ri], fenc(vFB));
            }
            if (g_sbg[b * PT + ri]) {
                atomicMax(&g_maxbf[b * PT + ri], fenc(vBF));
                atomicMin(&g_minbb[b * PT + ri], fenc(vBB));
            }
        }
    }
}

// -------- fused symmetric tiled similarity --------
__global__ void __launch_bounds__(256) k_sim() {
    __shared__ float As[DKC][TS];
    __shared__ float Bs[DKC][TS];
    __shared__ float sT[TS][TS + 1];

    int tid = threadIdx.x;
    int tx = tid & 15, ty = tid >> 4;
    int ldk = tid >> 4;            // 0..15 (dk row for loads)
    int lq  = (tid & 15) * 4;      // float4 column offset

    int total = g_item_off[BN];
    for (int item = blockIdx.x; item < total; item += SIM_BLOCKS) {
        int b = 0;
        while (b < BN - 1 && item >= g_item_off[b + 1]) b++;
        int local = item - g_item_off[b];
        int tiles = g_tiles[b];
        int rt = 0, rem = local;
        while (rem >= tiles - rt) { rem -= tiles - rt; rt++; }
        int ct = rt + rem;
        int Nb = g_Nb[b];
        int rowb = rt * TS, colb = ct * TS;

        float acc[4][4];
#pragma unroll
        for (int i = 0; i < 4; i++)
#pragma unroll
            for (int j = 0; j < 4; j++) acc[i][j] = 0.f;

        const float* Eb = g_Et + (size_t)b * DD * PT;
#pragma unroll 1
        for (int d0 = 0; d0 < DD; d0 += DKC) {
            // load 32 dk-rows x 64 pts, fully coalesced from transposed layout
#pragma unroll
            for (int h = 0; h < 2; h++) {
                int dk = ldk + 16 * h;
                const float* rsrc = Eb + (size_t)(d0 + dk) * PT;
                *(float4*)&As[dk][lq] = *(const float4*)(rsrc + rowb + lq);
                *(float4*)&Bs[dk][lq] = *(const float4*)(rsrc + colb + lq);
            }
            __syncthreads();
#pragma unroll
            for (int dk = 0; dk < DKC; dk++) {
                float4 a = *(const float4*)&As[dk][ty * 4];
                float4 c = *(const float4*)&Bs[dk][tx * 4];
                acc[0][0] += a.x * c.x; acc[0][1] += a.x * c.y; acc[0][2] += a.x * c.z; acc[0][3] += a.x * c.w;
                acc[1][0] += a.y * c.x; acc[1][1] += a.y * c.y; acc[1][2] += a.y * c.z; acc[1][3] += a.y * c.w;
                acc[2][0] += a.z * c.x; acc[2][1] += a.z * c.y; acc[2][2] += a.z * c.z; acc[2][3] += a.z * c.w;
                acc[3][0] += a.w * c.x; acc[3][1] += a.w * c.y; acc[3][2] += a.w * c.z; acc[3][3] += a.w * c.w;
            }
            __syncthreads();
        }

        // pass 1: rows = rowb tile, cols = colb tile
        route_tile(acc, b, rowb, colb, Nb, tx, ty);

        if (rt != ct) {
            // transpose via smem, route with swapped roles
#pragma unroll
            for (int i = 0; i < 4; i++)
#pragma unroll
                for (int j = 0; j < 4; j++)
                    sT[4 * tx + j][4 * ty + i] = acc[i][j];
            __syncthreads();
            float a2[4][4];
#pragma unroll
            for (int i = 0; i < 4; i++)
#pragma unroll
                for (int j = 0; j < 4; j++)
                    a2[i][j] = sT[4 * ty + i][4 * tx + j];
            route_tile(a2, b, colb, rowb, Nb, tx, ty);
        }
        __syncthreads();
    }
}

// -------- per-batch weighted means --------
__global__ void k_batch() {
    int b = blockIdx.x, tid = threadIdx.x;
    int Nb = g_Nb[b];
    float sff = 0.f, sfb = 0.f, sbb = 0.f, sbf = 0.f;
    for (int p = tid; p < Nb; p += 256) {
        if (g_sfg[b * PT + p]) {
            float wv = (float)g_sw[b * PT + p];
            sff += wv * fmaxf(THSIM - fdec(g_minff[b * PT + p]), 0.f);
            sfb += wv * fmaxf(fdec(g_maxfb[b * PT + p]) - THDIF, 0.f);
        }
        if (g_sbg[b * PT + p]) {
            sbb += fmaxf(THSIM - fdec(g_minbb[b * PT + p]), 0.f);
            sbf += fmaxf(fdec(g_maxbf[b * PT + p]) - THDIF, 0.f);
        }
    }
    __shared__ float r1[256], r2[256], r3[256], r4[256];
    r1[tid] = sff; r2[tid] = sfb; r3[tid] = sbb; r4[tid] = sbf;
    __syncthreads();
    for (int s = 128; s > 0; s >>= 1) {
        if (tid < s) {
            r1[tid] += r1[tid + s]; r2[tid] += r2[tid + s];
            r3[tid] += r3[tid + s]; r4[tid] += r4[tid + s];
        }
        __syncthreads();
    }
    if (tid == 0) {
        int cnt = g_bgcnt[b];
        float denf = fmaxf((float)g_sumw[b], 1.f);
        float denb = fmaxf((float)cnt, 1.f);
        float loss = r1[0] / denf + r2[0] / denf + r3[0] / denb + r4[0] / denb;
        g_perbatch[b] = (cnt > 0) ? loss : 0.f;
    }
}

__global__ void k_final(float* __restrict__ out) {
    if (threadIdx.x == 0) {
        float s = 0.f; int c = 0;
        for (int b = 0; b < BN; b++) { s += g_perbatch[b]; if (g_bgcnt[b] > 0) c++; }
        out[0] = s / fmaxf((float)c, 1.f);
    }
}

extern "C" void kernel_launch(void* const* d_in, const int* in_sizes, int n_in,
                              void* d_out, int out_size) {
    const float* emb    = (const float*)d_in[0];
    const float* cas    = (const float*)d_in[1];
    const int*   click  = (const int*)d_in[2];
    const int*   label  = (const int*)d_in[3];
    const int*   clsnum = (n_in >= 5) ? (const int*)d_in[4] : nullptr;

    k_topk   <<<dim3(CC, BN), 256>>>(cas);
    k_prep   <<<BN, 256>>>(click, label, clsnum);
    k_plan   <<<1, 32>>>();
    k_gatherT<<<dim3(16, BN), 256>>>(emb);
    k_norm   <<<dim3(PT / 256, BN), 256>>>();
    k_sim    <<<SIM_BLOCKS, 256>>>();
    k_batch  <<<BN, 256>>>();
    k_final  <<<1, 32>>>((float*)d_out);
}

// round 5
// speedup vs baseline: 4.6923x; 1.1887x over previous
#include <cuda_runtime.h>
#include <math.h>

#define BN 16
#define DD 512
#define TT 2048
#define CC 20
#define KK 7
#define FF (CC*KK)            // 140
#define PT 2048               // unique points live in t-space -> <= T
#define TS 64                 // similarity tile
#define DKC 32                // k-chunk
#define EPSV 1e-8f
#define BIGV 1e9f
#define THSIM 0.5f
#define THDIF 0.1f
#define SIM_BLOCKS 512

// -------- scratch (static device globals; no runtime allocation) --------
__device__ float    g_Et[(size_t)BN*DD*PT];   // transposed gathered points [b][d][p]
__device__ float    g_nrm[BN*PT];
__device__ int      g_fg_idx[BN*FF];
__device__ int      g_slotmap[BN*TT];         // t -> slot or -1
__device__ int      g_sw[BN*PT];              // per-slot fg multiplicity weight
__device__ unsigned char g_sfg[BN*PT];        // slot is masked-fg point
__device__ unsigned char g_sbg[BN*PT];        // slot is bg point
__device__ int      g_Nb[BN];
__device__ int      g_bgcnt[BN];
__device__ int      g_sumw[BN];
__device__ int      g_tiles[BN];
__device__ int      g_item_off[BN+1];
__device__ unsigned g_minff[BN*PT];
__device__ unsigned g_maxfb[BN*PT];
__device__ unsigned g_minbb[BN*PT];
__device__ unsigned g_maxbf[BN*PT];
__device__ float    g_perbatch[BN];

// monotonic float<->uint encoding: order-preserving, exact
__device__ __forceinline__ unsigned fenc(float f) {
    unsigned u = __float_as_uint(f);
    return (u & 0x80000000u) ? ~u : (u | 0x80000000u);
}
__device__ __forceinline__ float fdec(unsigned x) {
    return (x & 0x80000000u) ? __uint_as_float(x ^ 0x80000000u) : __uint_as_float(~x);
}

// -------- single-pass top-7: per-thread sorted list + tournament merge --------
__global__ void k_topk(const float* __restrict__ cas) {
    int c = blockIdx.x, b = blockIdx.y, tid = threadIdx.x;
    const float* row = cas + ((size_t)b * CC + c) * TT;

    float lv[KK]; int li[KK];
#pragma unroll
    for (int j = 0; j < KK; j++) { lv[j] = -INFINITY; li[j] = 0x7fffffff; }
    // each thread scans 8 strided elements, maintains sorted (desc value, asc idx) top-7
#pragma unroll
    for (int i = 0; i < 8; i++) {
        int t = tid + i * 256;
        float cv = row[t]; int ci = t;
#pragma unroll
        for (int j = 0; j < KK; j++) {
            bool better = (cv > lv[j]) || (cv == lv[j] && ci < li[j]);
            if (better) { float tv = lv[j]; int ti = li[j]; lv[j] = cv; li[j] = ci; cv = tv; ci = ti; }
        }
    }

    __shared__ float sv[256][KK];
    __shared__ int   si[256][KK];
#pragma unroll
    for (int j = 0; j < KK; j++) { sv[tid][j] = lv[j]; si[tid][j] = li[j]; }

    for (int s = 128; s > 0; s >>= 1) {
        __syncthreads();
        if (tid < s) {
            // merge sorted lists tid and tid+s -> top-7 into tid
            float mv[KK]; int mi[KK];
            int ia = 0, ib = 0;
#pragma unroll
            for (int j = 0; j < KK; j++) {
                float va = sv[tid][ia],     vb = sv[tid + s][ib];
                int   xa = si[tid][ia],     xb = si[tid + s][ib];
                bool takeA = (va > vb) || (va == vb && xa < xb);
                if (takeA) { mv[j] = va; mi[j] = xa; ia++; }
                else       { mv[j] = vb; mi[j] = xb; ib++; }
            }
#pragma unroll
            for (int j = 0; j < KK; j++) { sv[tid][j] = mv[j]; si[tid][j] = mi[j]; }
        }
    }
    __syncthreads();
    if (tid < KK) g_fg_idx[b * FF + c * KK + tid] = si[0][tid];
}

// -------- prep: unique-point slots, flags, weights, reduction init --------
__global__ void k_prep(const int* __restrict__ click, const int* __restrict__ label,
                       const int* __restrict__ clsnum) {
    int b = blockIdx.x, tid = threadIdx.x;
    int cn = clsnum ? clsnum[0] : CC;
    __shared__ int w[TT];
    __shared__ int woff[8];
    __shared__ int sbase, sbg;
    for (int t = tid; t < TT; t += 256) w[t] = 0;
    unsigned encBig = fenc(BIGV), encNeg = fenc(-BIGV);
    for (int p = tid; p < PT; p += 256) {
        g_minff[b * PT + p] = encBig;
        g_maxfb[b * PT + p] = encNeg;
        g_minbb[b * PT + p] = encBig;
        g_maxbf[b * PT + p] = encNeg;
    }
    if (tid == 0) { sbase = 0; sbg = 0; }
    __syncthreads();
    for (int i = tid; i < FF; i += 256) {
        int c = i / KK;
        if (label[b * CC + c] == 1) atomicAdd(&w[g_fg_idx[b * FF + i]], 1);
    }
    __syncthreads();
    for (int chunk = 0; chunk < TT; chunk += 256) {
        int t = chunk + tid;
        int bg  = (click[b * TT + t] == cn) ? 1 : 0;
        int wt  = w[t];
        int sel = (bg || wt > 0) ? 1 : 0;
        unsigned ball = __ballot_sync(0xffffffffu, sel);
        unsigned ballbg = __ballot_sync(0xffffffffu, bg);
        int wi = tid >> 5, lane = tid & 31;
        if (lane == 0) { woff[wi] = __popc(ball); atomicAdd(&sbg, __popc(ballbg)); }
        __syncthreads();
        if (tid == 0) {
            int s = sbase;
            for (int i = 0; i < 8; i++) { int cc2 = woff[i]; woff[i] = s; s += cc2; }
            sbase = s;
        }
        __syncthreads();
        if (sel) {
            int pos = woff[wi] + __popc(ball & ((1u << lane) - 1u));
            g_slotmap[b * TT + t] = pos;
            g_sw[b * PT + pos] = wt;
            g_sfg[b * PT + pos] = (wt > 0) ? 1 : 0;
            g_sbg[b * PT + pos] = (unsigned char)bg;
        } else {
            g_slotmap[b * TT + t] = -1;
        }
        __syncthreads();
    }
    if (tid == 0) {
        int numpos = 0;
        for (int c = 0; c < CC; c++) numpos += (label[b * CC + c] == 1) ? 1 : 0;
        g_sumw[b]  = KK * numpos;
        g_bgcnt[b] = sbg;
        g_Nb[b]    = sbase;
        g_tiles[b] = (sbase + TS - 1) / TS;
    }
}

__global__ void k_plan() {
    if (threadIdx.x == 0) {
        int off = 0;
        for (int b = 0; b < BN; b++) {
            int t = g_tiles[b];
            g_item_off[b] = off;
            off += t * (t + 1) / 2;
        }
        g_item_off[BN] = off;
    }
}

// -------- transpose-gather: 4 d-rows per block, float4 streaming --------
__global__ void k_gatherT(const float* __restrict__ emb) {
    int b = blockIdx.y, tid = threadIdx.x;
    int d0 = blockIdx.x * 4;
    __shared__ int smap[TT];
#pragma unroll
    for (int i = 0; i < 8; i++) smap[tid + i * 256] = g_slotmap[b * TT + tid + i * 256];
    __syncthreads();
#pragma unroll
    for (int dd = 0; dd < 4; dd++) {
        const float4* src4 = (const float4*)(emb + ((size_t)b * DD + d0 + dd) * TT);
        float* dst = g_Et + ((size_t)b * DD + d0 + dd) * PT;
#pragma unroll
        for (int it = 0; it < 2; it++) {
            int q = tid + it * 256;           // float4 index in [0,512)
            float4 v = src4[q];
            int t = q * 4;
            int s0 = smap[t], s1 = smap[t + 1], s2 = smap[t + 2], s3 = smap[t + 3];
            if (s0 >= 0) dst[s0] = v.x;
            if (s1 >= 0) dst[s1] = v.y;
            if (s2 >= 0) dst[s2] = v.z;
            if (s3 >= 0) dst[s3] = v.w;
        }
    }
}

// -------- per-slot norms: coalesced column-walk of Et --------
__global__ void k_norm() {
    int b = blockIdx.y;
    int p = blockIdx.x * 256 + threadIdx.x;
    if (p >= g_Nb[b]) return;
    const float* base = g_Et + (size_t)b * DD * PT + p;
    float s = 0.f;
#pragma unroll 8
    for (int d = 0; d < DD; d++) {
        float v = base[(size_t)d * PT];
        s += v * v;
    }
    g_nrm[b * PT + p] = sqrtf(s);
}

// -------- routing: per-row min/max over typed columns, atomic-merged --------
__device__ __forceinline__ void route_tile(const float acc[4][4], int b,
                                           int rowb, int colb, int Nb,
                                           int tx, int ty) {
    float nc[4]; int cfg[4], cbg[4];
#pragma unroll
    for (int j = 0; j < 4; j++) {
        int c = colb + 4 * tx + j;
        bool cok = (c < Nb);
        nc[j]  = g_nrm[b * PT + c];
        cfg[j] = cok && g_sfg[b * PT + c];
        cbg[j] = cok && g_sbg[b * PT + c];
    }
#pragma unroll
    for (int i = 0; i < 4; i++) {
        int ri = rowb + 4 * ty + i;
        float nr = g_nrm[b * PT + ri];
        float vFF = BIGV, vBF = -BIGV, vFB = -BIGV, vBB = BIGV;
#pragma unroll
        for (int j = 0; j < 4; j++) {
            float cs = acc[i][j] / fmaxf(nr * nc[j], EPSV);
            if (cfg[j]) { vFF = fminf(vFF, cs); vBF = fmaxf(vBF, cs); }
            if (cbg[j]) { vFB = fmaxf(vFB, cs); vBB = fminf(vBB, cs); }
        }
#pragma unroll
        for (int m = 8; m > 0; m >>= 1) {
            vFF = fminf(vFF, __shfl_xor_sync(0xffffffffu, vFF, m));
            vBF = fmaxf(vBF, __shfl_xor_sync(0xffffffffu, vBF, m));
            vFB = fmaxf(vFB, __shfl_xor_sync(0xffffffffu, vFB, m));
            vBB = fminf(vBB, __shfl_xor_sync(0xffffffffu, vBB, m));
        }
        if (tx == 0 && ri < Nb) {
            if (g_sfg[b * PT + ri]) {
                atomicMin(&g_minff[b * PT + ri], fenc(vFF));
                atomicMax(&g_maxfb[b * PT + ri], fenc(vFB));
            }
            if (g_sbg[b * PT + ri]) {
                atomicMax(&g_maxbf[b * PT + ri], fenc(vBF));
                atomicMin(&g_minbb[b * PT + ri], fenc(vBB));
            }
        }
    }
}

// -------- fused symmetric tiled similarity --------
__global__ void __launch_bounds__(256) k_sim() {
    __shared__ float As[DKC][TS];
    __shared__ float Bs[DKC][TS];
    __shared__ float sT[TS][TS + 1];

    int tid = threadIdx.x;
    int tx = tid & 15, ty = tid >> 4;
    int ldk = tid >> 4;            // 0..15 (dk row for loads)
    int lq  = (tid & 15) * 4;      // float4 column offset

    int total = g_item_off[BN];
    for (int item = blockIdx.x; item < total; item += SIM_BLOCKS) {
        int b = 0;
        while (b < BN - 1 && item >= g_item_off[b + 1]) b++;
        int local = item - g_item_off[b];
        int tiles = g_tiles[b];
        int rt = 0, rem = local;
        while (rem >= tiles - rt) { rem -= tiles - rt; rt++; }
        int ct = rt + rem;
        int Nb = g_Nb[b];
        int rowb = rt * TS, colb = ct * TS;

        float acc[4][4];
#pragma unroll
        for (int i = 0; i < 4; i++)
#pragma unroll
            for (int j = 0; j < 4; j++) acc[i][j] = 0.f;

        const float* Eb = g_Et + (size_t)b * DD * PT;
#pragma unroll 1
        for (int d0 = 0; d0 < DD; d0 += DKC) {
#pragma unroll
            for (int h = 0; h < 2; h++) {
                int dk = ldk + 16 * h;
                const float* rsrc = Eb + (size_t)(d0 + dk) * PT;
                *(float4*)&As[dk][lq] = *(const float4*)(rsrc + rowb + lq);
                *(float4*)&Bs[dk][lq] = *(const float4*)(rsrc + colb + lq);
            }
            __syncthreads();
#pragma unroll
            for (int dk = 0; dk < DKC; dk++) {
                float4 a = *(const float4*)&As[dk][ty * 4];
                float4 c = *(const float4*)&Bs[dk][tx * 4];
                acc[0][0] += a.x * c.x; acc[0][1] += a.x * c.y; acc[0][2] += a.x * c.z; acc[0][3] += a.x * c.w;
                acc[1][0] += a.y * c.x; acc[1][1] += a.y * c.y; acc[1][2] += a.y * c.z; acc[1][3] += a.y * c.w;
                acc[2][0] += a.z * c.x; acc[2][1] += a.z * c.y; acc[2][2] += a.z * c.z; acc[2][3] += a.z * c.w;
                acc[3][0] += a.w * c.x; acc[3][1] += a.w * c.y; acc[3][2] += a.w * c.z; acc[3][3] += a.w * c.w;
            }
            __syncthreads();
        }

        route_tile(acc, b, rowb, colb, Nb, tx, ty);

        if (rt != ct) {
#pragma unroll
            for (int i = 0; i < 4; i++)
#pragma unroll
                for (int j = 0; j < 4; j++)
                    sT[4 * tx + j][4 * ty + i] = acc[i][j];
            __syncthreads();
            float a2[4][4];
#pragma unroll
            for (int i = 0; i < 4; i++)
#pragma unroll
                for (int j = 0; j < 4; j++)
                    a2[i][j] = sT[4 * ty + i][4 * tx + j];
            route_tile(a2, b, colb, rowb, Nb, tx, ty);
        }
        __syncthreads();
    }
}

// -------- per-batch weighted means --------
__global__ void k_batch() {
    int b = blockIdx.x, tid = threadIdx.x;
    int Nb = g_Nb[b];
    float sff = 0.f, sfb = 0.f, sbb = 0.f, sbf = 0.f;
    for (int p = tid; p < Nb; p += 256) {
        if (g_sfg[b * PT + p]) {
            float wv = (float)g_sw[b * PT + p];
            sff += wv * fmaxf(THSIM - fdec(g_minff[b * PT + p]), 0.f);
            sfb += wv * fmaxf(fdec(g_maxfb[b * PT + p]) - THDIF, 0.f);
        }
        if (g_sbg[b * PT + p]) {
            sbb += fmaxf(THSIM - fdec(g_minbb[b * PT + p]), 0.f);
            sbf += fmaxf(fdec(g_maxbf[b * PT + p]) - THDIF, 0.f);
        }
    }
    __shared__ float r1[256], r2[256], r3[256], r4[256];
    r1[tid] = sff; r2[tid] = sfb; r3[tid] = sbb; r4[tid] = sbf;
    __syncthreads();
    for (int s = 128; s > 0; s >>= 1) {
        if (tid < s) {
            r1[tid] += r1[tid + s]; r2[tid] += r2[tid + s];
            r3[tid] += r3[tid + s]; r4[tid] += r4[tid + s];
        }
        __syncthreads();
    }
    if (tid == 0) {
        int cnt = g_bgcnt[b];
        float denf = fmaxf((float)g_sumw[b], 1.f);
        float denb = fmaxf((float)cnt, 1.f);
        float loss = r1[0] / denf + r2[0] / denf + r3[0] / denb + r4[0] / denb;
        g_perbatch[b] = (cnt > 0) ? loss : 0.f;
    }
}

__global__ void k_final(float* __restrict__ out) {
    if (threadIdx.x == 0) {
        float s = 0.f; int c = 0;
        for (int b = 0; b < BN; b++) { s += g_perbatch[b]; if (g_bgcnt[b] > 0) c++; }
        out[0] = s / fmaxf((float)c, 1.f);
    }
}

extern "C" void kernel_launch(void* const* d_in, const int* in_sizes, int n_in,
                              void* d_out, int out_size) {
    const float* emb    = (const float*)d_in[0];
    const float* cas    = (const float*)d_in[1];
    const int*   click  = (const int*)d_in[2];
    const int*   label  = (const int*)d_in[3];
    const int*   clsnum = (n_in >= 5) ? (const int*)d_in[4] : nullptr;

    k_topk   <<<dim3(CC, BN), 256>>>(cas);
    k_prep   <<<BN, 256>>>(click, label, clsnum);
    k_plan   <<<1, 32>>>();
    k_gatherT<<<dim3(DD / 4, BN), 256>>>(emb);
    k_norm   <<<dim3(PT / 256, BN), 256>>>();
    k_sim    <<<SIM_BLOCKS, 256>>>();
    k_batch  <<<BN, 256>>>();
    k_final  <<<1, 32>>>((float*)d_out);
}

// round 6
// speedup vs baseline: 5.6699x; 1.2083x over previous
#include <cuda_runtime.h>
#include <math.h>

#define BN 16
#define DD 512
#define TT 2048
#define CC 20
#define KK 7
#define FF (CC*KK)            // 140
#define PT 2048
#define TS 32                 // similarity tile
#define DKC 32                // k-chunk
#define EPSV 1e-8f
#define BIGV 1e9f
#define THSIM 0.5f
#define THDIF 0.1f
#define SIM_BLOCKS 1184

// -------- scratch (static device globals; no runtime allocation) --------
__device__ float    g_Et[(size_t)BN*DD*PT];   // transposed gathered points [b][d][p]
__device__ float    g_nrm[BN*PT];
__device__ int      g_fg_idx[BN*FF];
__device__ int      g_slotmap[BN*TT];
__device__ int      g_sw[BN*PT];
__device__ unsigned char g_sfg[BN*PT];
__device__ unsigned char g_sbg[BN*PT];
__device__ int      g_Nb[BN];
__device__ int      g_bgcnt[BN];
__device__ int      g_sumw[BN];
__device__ int      g_tiles[BN];
__device__ unsigned g_minff[BN*PT];
__device__ unsigned g_maxfb[BN*PT];
__device__ unsigned g_minbb[BN*PT];
__device__ unsigned g_maxbf[BN*PT];
__device__ float    g_perbatch[BN];
__device__ int      g_ticket;

__device__ __forceinline__ unsigned fenc(float f) {
    unsigned u = __float_as_uint(f);
    return (u & 0x80000000u) ? ~u : (u | 0x80000000u);
}
__device__ __forceinline__ float fdec(unsigned x) {
    return (x & 0x80000000u) ? __uint_as_float(x ^ 0x80000000u) : __uint_as_float(~x);
}

// -------- single-pass top-7: per-thread sorted list + tournament merge --------
__global__ void k_topk(const float* __restrict__ cas) {
    int c = blockIdx.x, b = blockIdx.y, tid = threadIdx.x;
    const float* row = cas + ((size_t)b * CC + c) * TT;

    float lv[KK]; int li[KK];
#pragma unroll
    for (int j = 0; j < KK; j++) { lv[j] = -INFINITY; li[j] = 0x7fffffff; }
#pragma unroll
    for (int i = 0; i < 8; i++) {
        int t = tid + i * 256;
        float cv = row[t]; int ci = t;
#pragma unroll
        for (int j = 0; j < KK; j++) {
            bool better = (cv > lv[j]) || (cv == lv[j] && ci < li[j]);
            if (better) { float tv = lv[j]; int ti = li[j]; lv[j] = cv; li[j] = ci; cv = tv; ci = ti; }
        }
    }

    __shared__ float sv[256][KK];
    __shared__ int   si[256][KK];
#pragma unroll
    for (int j = 0; j < KK; j++) { sv[tid][j] = lv[j]; si[tid][j] = li[j]; }

    for (int s = 128; s > 0; s >>= 1) {
        __syncthreads();
        if (tid < s) {
            float mv[KK]; int mi[KK];
            int ia = 0, ib = 0;
#pragma unroll
            for (int j = 0; j < KK; j++) {
                float va = sv[tid][ia],     vb = sv[tid + s][ib];
                int   xa = si[tid][ia],     xb = si[tid + s][ib];
                bool takeA = (va > vb) || (va == vb && xa < xb);
                if (takeA) { mv[j] = va; mi[j] = xa; ia++; }
                else       { mv[j] = vb; mi[j] = xb; ib++; }
            }
#pragma unroll
            for (int j = 0; j < KK; j++) { sv[tid][j] = mv[j]; si[tid][j] = mi[j]; }
        }
    }
    __syncthreads();
    if (tid < KK) g_fg_idx[b * FF + c * KK + tid] = si[0][tid];
}

// -------- prep: unique-point slots, flags, weights, reduction init --------
__global__ void k_prep(const int* __restrict__ click, const int* __restrict__ label,
                       const int* __restrict__ clsnum) {
    int b = blockIdx.x, tid = threadIdx.x;
    int cn = clsnum ? clsnum[0] : CC;
    __shared__ int w[TT];
    __shared__ int woff[8];
    __shared__ int sbase, sbg;
    for (int t = tid; t < TT; t += 256) w[t] = 0;
    unsigned encBig = fenc(BIGV), encNeg = fenc(-BIGV);
    for (int p = tid; p < PT; p += 256) {
        g_minff[b * PT + p] = encBig;
        g_maxfb[b * PT + p] = encNeg;
        g_minbb[b * PT + p] = encBig;
        g_maxbf[b * PT + p] = encNeg;
    }
    if (tid == 0) { sbase = 0; sbg = 0; }
    __syncthreads();
    for (int i = tid; i < FF; i += 256) {
        int c = i / KK;
        if (label[b * CC + c] == 1) atomicAdd(&w[g_fg_idx[b * FF + i]], 1);
    }
    __syncthreads();
    for (int chunk = 0; chunk < TT; chunk += 256) {
        int t = chunk + tid;
        int bg  = (click[b * TT + t] == cn) ? 1 : 0;
        int wt  = w[t];
        int sel = (bg || wt > 0) ? 1 : 0;
        unsigned ball = __ballot_sync(0xffffffffu, sel);
        unsigned ballbg = __ballot_sync(0xffffffffu, bg);
        int wi = tid >> 5, lane = tid & 31;
        if (lane == 0) { woff[wi] = __popc(ball); atomicAdd(&sbg, __popc(ballbg)); }
        __syncthreads();
        if (tid == 0) {
            int s = sbase;
            for (int i = 0; i < 8; i++) { int cc2 = woff[i]; woff[i] = s; s += cc2; }
            sbase = s;
        }
        __syncthreads();
        if (sel) {
            int pos = woff[wi] + __popc(ball & ((1u << lane) - 1u));
            g_slotmap[b * TT + t] = pos;
            g_sw[b * PT + pos] = wt;
            g_sfg[b * PT + pos] = (wt > 0) ? 1 : 0;
            g_sbg[b * PT + pos] = (unsigned char)bg;
        } else {
            g_slotmap[b * TT + t] = -1;
        }
        __syncthreads();
    }
    if (tid == 0) {
        int numpos = 0;
        for (int c = 0; c < CC; c++) numpos += (label[b * CC + c] == 1) ? 1 : 0;
        g_sumw[b]  = KK * numpos;
        g_bgcnt[b] = sbg;
        g_Nb[b]    = sbase;
        g_tiles[b] = (sbase + TS - 1) / TS;
    }
}

// -------- transpose-gather: 4 d-rows/block, 8 loads in flight, shared slotmap --------
__global__ void k_gatherT(const float* __restrict__ emb) {
    int b = blockIdx.y, tid = threadIdx.x;
    int d0 = blockIdx.x * 4;
    __shared__ int smap[TT];
#pragma unroll
    for (int i = 0; i < 8; i++) smap[tid + i * 256] = g_slotmap[b * TT + tid + i * 256];
    __syncthreads();

    const float4* src = (const float4*)(emb + ((size_t)b * DD + d0) * TT);
    float4 v[8];
#pragma unroll
    for (int dd = 0; dd < 4; dd++) {
#pragma unroll
        for (int it = 0; it < 2; it++)
            v[dd * 2 + it] = src[dd * (TT / 4) + tid + it * 256];
    }
    int sA[4], sB[4];
    {
        int t0 = tid * 4, t1 = (tid + 256) * 4;
#pragma unroll
        for (int j = 0; j < 4; j++) { sA[j] = smap[t0 + j]; sB[j] = smap[t1 + j]; }
    }
#pragma unroll
    for (int dd = 0; dd < 4; dd++) {
        float* dst = g_Et + ((size_t)b * DD + d0 + dd) * PT;
        float4 a = v[dd * 2], c = v[dd * 2 + 1];
        if (sA[0] >= 0) dst[sA[0]] = a.x;
        if (sA[1] >= 0) dst[sA[1]] = a.y;
        if (sA[2] >= 0) dst[sA[2]] = a.z;
        if (sA[3] >= 0) dst[sA[3]] = a.w;
        if (sB[0] >= 0) dst[sB[0]] = c.x;
        if (sB[1] >= 0) dst[sB[1]] = c.y;
        if (sB[2] >= 0) dst[sB[2]] = c.z;
        if (sB[3] >= 0) dst[sB[3]] = c.w;
    }
}

// -------- per-slot norms --------
__global__ void k_norm() {
    int b = blockIdx.y;
    int p = blockIdx.x * 256 + threadIdx.x;
    if (p >= g_Nb[b]) return;
    const float* base = g_Et + (size_t)b * DD * PT + p;
    float s = 0.f;
#pragma unroll 16
    for (int d = 0; d < DD; d++) {
        float v = base[(size_t)d * PT];
        s += v * v;
    }
    g_nrm[b * PT + p] = sqrtf(s);
}

// -------- routing: per-row min/max over typed columns, atomic-merged --------
__device__ __forceinline__ void route_tile(const float acc[4][4], int b,
                                           int rowb, int colb, int Nb,
                                           int tx, int ty) {
    float nc[4]; int cfg[4], cbg[4];
#pragma unroll
    for (int j = 0; j < 4; j++) {
        int c = colb + 4 * tx + j;
        bool cok = (c < Nb);
        nc[j]  = g_nrm[b * PT + c];
        cfg[j] = cok && g_sfg[b * PT + c];
        cbg[j] = cok && g_sbg[b * PT + c];
    }
#pragma unroll
    for (int i = 0; i < 4; i++) {
        int ri = rowb + 4 * ty + i;
        float nr = g_nrm[b * PT + ri];
        float vFF = BIGV, vBF = -BIGV, vFB = -BIGV, vBB = BIGV;
#pragma unroll
        for (int j = 0; j < 4; j++) {
            float cs = acc[i][j] / fmaxf(nr * nc[j], EPSV);
            if (cfg[j]) { vFF = fminf(vFF, cs); vBF = fmaxf(vBF, cs); }
            if (cbg[j]) { vFB = fmaxf(vFB, cs); vBB = fminf(vBB, cs); }
        }
#pragma unroll
        for (int m = 4; m > 0; m >>= 1) {     // reduce over tx (8 lanes, low 3 lane bits)
            vFF = fminf(vFF, __shfl_xor_sync(0xffffffffu, vFF, m));
            vBF = fmaxf(vBF, __shfl_xor_sync(0xffffffffu, vBF, m));
            vFB = fmaxf(vFB, __shfl_xor_sync(0xffffffffu, vFB, m));
            vBB = fminf(vBB, __shfl_xor_sync(0xffffffffu, vBB, m));
        }
        if (tx == 0 && ri < Nb) {
            if (g_sfg[b * PT + ri]) {
                atomicMin(&g_minff[b * PT + ri], fenc(vFF));
                atomicMax(&g_maxfb[b * PT + ri], fenc(vFB));
            }
            if (g_sbg[b * PT + ri]) {
                atomicMax(&g_maxbf[b * PT + ri], fenc(vBF));
                atomicMin(&g_minbb[b * PT + ri], fenc(vBB));
            }
        }
    }
}

// -------- fused symmetric tiled similarity: 32x32 tiles, 64-thread blocks --------
__global__ void __launch_bounds__(64) k_sim() {
    __shared__ float As[DKC][TS];
    __shared__ float Bs[DKC][TS];
    __shared__ float sT[TS][TS + 1];
    __shared__ int   s_off[BN + 1];

    int tid = threadIdx.x;
    int tx = tid & 7, ty = tid >> 3;

    if (tid == 0) {
        int off = 0;
        for (int b = 0; b < BN; b++) { s_off[b] = off; int t = g_tiles[b]; off += t * (t + 1) / 2; }
        s_off[BN] = off;
    }
    __syncthreads();
    int total = s_off[BN];

    for (int item = blockIdx.x; item < total; item += gridDim.x) {
        int b = 0;
        while (b < BN - 1 && item >= s_off[b + 1]) b++;
        int local = item - s_off[b];
        int tiles = g_tiles[b];
        int rt = 0, rem = local;
        while (rem >= tiles - rt) { rem -= tiles - rt; rt++; }
        int ct = rt + rem;
        int Nb = g_Nb[b];
        int rowb = rt * TS, colb = ct * TS;

        float acc[4][4];
#pragma unroll
        for (int i = 0; i < 4; i++)
#pragma unroll
            for (int j = 0; j < 4; j++) acc[i][j] = 0.f;

        const float* Eb = g_Et + (size_t)b * DD * PT;
#pragma unroll 1
        for (int d0 = 0; d0 < DD; d0 += DKC) {
            // stage 32dk x 32p per buffer: 4 coalesced float4 loads per thread
#pragma unroll
            for (int i = 0; i < 4; i++) {
                int lin = i * 64 + tid;            // 0..255
                int dk = lin >> 3, pq = (lin & 7) * 4;
                const float* rsrc = Eb + (size_t)(d0 + dk) * PT;
                *(float4*)&As[dk][pq] = *(const float4*)(rsrc + rowb + pq);
                *(float4*)&Bs[dk][pq] = *(const float4*)(rsrc + colb + pq);
            }
            __syncthreads();
#pragma unroll
            for (int dk = 0; dk < DKC; dk++) {
                float4 a = *(const float4*)&As[dk][ty * 4];
                float4 c = *(const float4*)&Bs[dk][tx * 4];
                acc[0][0] += a.x * c.x; acc[0][1] += a.x * c.y; acc[0][2] += a.x * c.z; acc[0][3] += a.x * c.w;
                acc[1][0] += a.y * c.x; acc[1][1] += a.y * c.y; acc[1][2] += a.y * c.z; acc[1][3] += a.y * c.w;
                acc[2][0] += a.z * c.x; acc[2][1] += a.z * c.y; acc[2][2] += a.z * c.z; acc[2][3] += a.z * c.w;
                acc[3][0] += a.w * c.x; acc[3][1] += a.w * c.y; acc[3][2] += a.w * c.z; acc[3][3] += a.w * c.w;
            }
            __syncthreads();
        }

        route_tile(acc, b, rowb, colb, Nb, tx, ty);

        if (rt != ct) {
#pragma unroll
            for (int i = 0; i < 4; i++)
#pragma unroll
                for (int j = 0; j < 4; j++)
                    sT[4 * tx + j][4 * ty + i] = acc[i][j];
            __syncthreads();
            float a2[4][4];
#pragma unroll
            for (int i = 0; i < 4; i++)
#pragma unroll
                for (int j = 0; j < 4; j++)
                    a2[i][j] = sT[4 * ty + i][4 * tx + j];
            __syncthreads();
            route_tile(a2, b, colb, rowb, Nb, tx, ty);
        }
    }
}

// -------- per-batch weighted means + fused final (last-block ticket) --------
__global__ void k_batch(float* __restrict__ out) {
    int b = blockIdx.x, tid = threadIdx.x;
    int Nb = g_Nb[b];
    float sff = 0.f, sfb = 0.f, sbb = 0.f, sbf = 0.f;
    for (int p = tid; p < Nb; p += 256) {
        if (g_sfg[b * PT + p]) {
            float wv = (float)g_sw[b * PT + p];
            sff += wv * fmaxf(THSIM - fdec(g_minff[b * PT + p]), 0.f);
            sfb += wv * fmaxf(fdec(g_maxfb[b * PT + p]) - THDIF, 0.f);
        }
        if (g_sbg[b * PT + p]) {
            sbb += fmaxf(THSIM - fdec(g_minbb[b * PT + p]), 0.f);
            sbf += fmaxf(fdec(g_maxbf[b * PT + p]) - THDIF, 0.f);
        }
    }
    __shared__ float r1[256], r2[256], r3[256], r4[256];
    __shared__ int s_last;
    r1[tid] = sff; r2[tid] = sfb; r3[tid] = sbb; r4[tid] = sbf;
    __syncthreads();
    for (int s = 128; s > 0; s >>= 1) {
        if (tid < s) {
            r1[tid] += r1[tid + s]; r2[tid] += r2[tid + s];
            r3[tid] += r3[tid + s]; r4[tid] += r4[tid + s];
        }
        __syncthreads();
    }
    if (tid == 0) {
        int cnt = g_bgcnt[b];
        float denf = fmaxf((float)g_sumw[b], 1.f);
        float denb = fmaxf((float)cnt, 1.f);
        float loss = r1[0] / denf + r2[0] / denf + r3[0] / denb + r4[0] / denb;
        g_perbatch[b] = (cnt > 0) ? loss : 0.f;
        __threadfence();
        int old = atomicAdd(&g_ticket, 1);
        s_last = (old == BN - 1) ? 1 : 0;
    }
    __syncthreads();
    if (s_last && tid == 0) {
        volatile float* pb = g_perbatch;
        float s = 0.f; int c = 0;
        for (int bb = 0; bb < BN; bb++) { s += pb[bb]; if (g_bgcnt[bb] > 0) c++; }
        out[0] = s / fmaxf((float)c, 1.f);
        g_ticket = 0;   // reset for next graph replay
    }
}

extern "C" void kernel_launch(void* const* d_in, const int* in_sizes, int n_in,
                              void* d_out, int out_size) {
    const float* emb    = (const float*)d_in[0];
    const float* cas    = (const float*)d_in[1];
    const int*   click  = (const int*)d_in[2];
    const int*   label  = (const int*)d_in[3];
    const int*   clsnum = (n_in >= 5) ? (const int*)d_in[4] : nullptr;

    k_topk   <<<dim3(CC, BN), 256>>>(cas);
    k_prep   <<<BN, 256>>>(click, label, clsnum);
    k_gatherT<<<dim3(DD / 4, BN), 256>>>(emb);
    k_norm   <<<dim3(PT / 256, BN), 256>>>();
    k_sim    <<<SIM_BLOCKS, 64>>>();
    k_batch  <<<BN, 256>>>((float*)d_out);
}

// round 7
// speedup vs baseline: 6.5977x; 1.1636x over previous
#include <cuda_runtime.h>
#include <math.h>

#define BN 16
#define DD 512
#define TT 2048
#define CC 20
#define KK 7
#define FF (CC*KK)            // 140
#define PT 2048
#define TS 32                 // similarity tile
#define DKC 32                // k-chunk
#define EPSV 1e-8f
#define BIGV 1e9f
#define THSIM 0.5f
#define THDIF 0.1f
#define SIM_BLOCKS 1184

// -------- scratch (static device globals; no runtime allocation) --------
__device__ float    g_Et[(size_t)BN*DD*PT];   // transposed gathered points [b][d][p]
__device__ float    g_nrm[BN*PT];
__device__ int      g_fg_idx[BN*FF];
__device__ int      g_slotmap[BN*TT];
__device__ int      g_sw[BN*PT];
__device__ unsigned char g_sfg[BN*PT];
__device__ unsigned char g_sbg[BN*PT];
__device__ int      g_Nb[BN];
__device__ int      g_bgcnt[BN];
__device__ int      g_sumw[BN];
__device__ int      g_tiles[BN];
__device__ unsigned g_minff[BN*PT];
__device__ unsigned g_maxfb[BN*PT];
__device__ unsigned g_minbb[BN*PT];
__device__ unsigned g_maxbf[BN*PT];
__device__ float    g_perbatch[BN];
__device__ int      g_ticket;

__device__ __forceinline__ unsigned fenc(float f) {
    unsigned u = __float_as_uint(f);
    return (u & 0x80000000u) ? ~u : (u | 0x80000000u);
}
__device__ __forceinline__ float fdec(unsigned x) {
    return (x & 0x80000000u) ? __uint_as_float(x ^ 0x80000000u) : __uint_as_float(~x);
}

// -------- single-pass top-7: per-thread sorted list + tournament merge --------
__global__ void k_topk(const float* __restrict__ cas) {
    int c = blockIdx.x, b = blockIdx.y, tid = threadIdx.x;
    const float* row = cas + ((size_t)b * CC + c) * TT;

    float lv[KK]; int li[KK];
#pragma unroll
    for (int j = 0; j < KK; j++) { lv[j] = -INFINITY; li[j] = 0x7fffffff; }
#pragma unroll
    for (int i = 0; i < 8; i++) {
        int t = tid + i * 256;
        float cv = row[t]; int ci = t;
#pragma unroll
        for (int j = 0; j < KK; j++) {
            bool better = (cv > lv[j]) || (cv == lv[j] && ci < li[j]);
            if (better) { float tv = lv[j]; int ti = li[j]; lv[j] = cv; li[j] = ci; cv = tv; ci = ti; }
        }
    }

    __shared__ float sv[256][KK];
    __shared__ int   si[256][KK];
#pragma unroll
    for (int j = 0; j < KK; j++) { sv[tid][j] = lv[j]; si[tid][j] = li[j]; }

    for (int s = 128; s > 0; s >>= 1) {
        __syncthreads();
        if (tid < s) {
            float mv[KK]; int mi[KK];
            int ia = 0, ib = 0;
#pragma unroll
            for (int j = 0; j < KK; j++) {
                float va = sv[tid][ia],     vb = sv[tid + s][ib];
                int   xa = si[tid][ia],     xb = si[tid + s][ib];
                bool takeA = (va > vb) || (va == vb && xa < xb);
                if (takeA) { mv[j] = va; mi[j] = xa; ia++; }
                else       { mv[j] = vb; mi[j] = xb; ib++; }
            }
#pragma unroll
            for (int j = 0; j < KK; j++) { sv[tid][j] = mv[j]; si[tid][j] = mi[j]; }
        }
    }
    __syncthreads();
    if (tid < KK) g_fg_idx[b * FF + c * KK + tid] = si[0][tid];
}

// -------- prep: unique-point slots, flags, weights, reduction init --------
__global__ void k_prep(const int* __restrict__ click, const int* __restrict__ label,
                       const int* __restrict__ clsnum) {
    int b = blockIdx.x, tid = threadIdx.x;
    int cn = clsnum ? clsnum[0] : CC;
    __shared__ int w[TT];
    __shared__ int woff[8];
    __shared__ int sbase, sbg;
    for (int t = tid; t < TT; t += 256) w[t] = 0;
    unsigned encBig = fenc(BIGV), encNeg = fenc(-BIGV);
    for (int p = tid; p < PT; p += 256) {
        g_minff[b * PT + p] = encBig;
        g_maxfb[b * PT + p] = encNeg;
        g_minbb[b * PT + p] = encBig;
        g_maxbf[b * PT + p] = encNeg;
    }
    if (tid == 0) { sbase = 0; sbg = 0; }
    __syncthreads();
    for (int i = tid; i < FF; i += 256) {
        int c = i / KK;
        if (label[b * CC + c] == 1) atomicAdd(&w[g_fg_idx[b * FF + i]], 1);
    }
    __syncthreads();
    for (int chunk = 0; chunk < TT; chunk += 256) {
        int t = chunk + tid;
        int bg  = (click[b * TT + t] == cn) ? 1 : 0;
        int wt  = w[t];
        int sel = (bg || wt > 0) ? 1 : 0;
        unsigned ball = __ballot_sync(0xffffffffu, sel);
        unsigned ballbg = __ballot_sync(0xffffffffu, bg);
        int wi = tid >> 5, lane = tid & 31;
        if (lane == 0) { woff[wi] = __popc(ball); atomicAdd(&sbg, __popc(ballbg)); }
        __syncthreads();
        if (tid == 0) {
            int s = sbase;
            for (int i = 0; i < 8; i++) { int cc2 = woff[i]; woff[i] = s; s += cc2; }
            sbase = s;
        }
        __syncthreads();
        if (sel) {
            int pos = woff[wi] + __popc(ball & ((1u << lane) - 1u));
            g_slotmap[b * TT + t] = pos;
            g_sw[b * PT + pos] = wt;
            g_sfg[b * PT + pos] = (wt > 0) ? 1 : 0;
            g_sbg[b * PT + pos] = (unsigned char)bg;
        } else {
            g_slotmap[b * TT + t] = -1;
        }
        __syncthreads();
    }
    if (tid == 0) {
        int numpos = 0;
        for (int c = 0; c < CC; c++) numpos += (label[b * CC + c] == 1) ? 1 : 0;
        g_sumw[b]  = KK * numpos;
        g_bgcnt[b] = sbg;
        g_Nb[b]    = sbase;
        g_tiles[b] = (sbase + TS - 1) / TS;
    }
}

// -------- transpose-gather: 4 d-rows/block, 8 loads in flight, shared slotmap --------
__global__ void k_gatherT(const float* __restrict__ emb) {
    int b = blockIdx.y, tid = threadIdx.x;
    int d0 = blockIdx.x * 4;
    __shared__ int smap[TT];
#pragma unroll
    for (int i = 0; i < 8; i++) smap[tid + i * 256] = g_slotmap[b * TT + tid + i * 256];
    __syncthreads();

    const float4* src = (const float4*)(emb + ((size_t)b * DD + d0) * TT);
    float4 v[8];
#pragma unroll
    for (int dd = 0; dd < 4; dd++) {
#pragma unroll
        for (int it = 0; it < 2; it++)
            v[dd * 2 + it] = src[dd * (TT / 4) + tid + it * 256];
    }
    int sA[4], sB[4];
    {
        int t0 = tid * 4, t1 = (tid + 256) * 4;
#pragma unroll
        for (int j = 0; j < 4; j++) { sA[j] = smap[t0 + j]; sB[j] = smap[t1 + j]; }
    }
#pragma unroll
    for (int dd = 0; dd < 4; dd++) {
        float* dst = g_Et + ((size_t)b * DD + d0 + dd) * PT;
        float4 a = v[dd * 2], c = v[dd * 2 + 1];
        if (sA[0] >= 0) dst[sA[0]] = a.x;
        if (sA[1] >= 0) dst[sA[1]] = a.y;
        if (sA[2] >= 0) dst[sA[2]] = a.z;
        if (sA[3] >= 0) dst[sA[3]] = a.w;
        if (sB[0] >= 0) dst[sB[0]] = c.x;
        if (sB[1] >= 0) dst[sB[1]] = c.y;
        if (sB[2] >= 0) dst[sB[2]] = c.z;
        if (sB[3] >= 0) dst[sB[3]] = c.w;
    }
}

// -------- per-slot norms: 32 points/block, d split across 8 warps --------
__global__ void __launch_bounds__(256) k_norm() {
    int b = blockIdx.y;
    int pbase = blockIdx.x * 32;
    int Nb = g_Nb[b];
    if (pbase >= Nb) return;                 // uniform for whole block
    int w = threadIdx.x >> 5, lane = threadIdx.x & 31;
    int p = pbase + lane;

    const float* base = g_Et + (size_t)b * DD * PT + (size_t)(w * 64) * PT + p;
    float s = 0.f;
#pragma unroll 16
    for (int i = 0; i < 64; i++) {
        float v = base[(size_t)i * PT];
        s += v * v;
    }
    __shared__ float part[8][32];
    part[w][lane] = s;
    __syncthreads();
    if (w == 0) {
        float acc = part[0][lane];
#pragma unroll
        for (int k = 1; k < 8; k++) acc += part[k][lane];
        if (p < Nb) g_nrm[b * PT + p] = sqrtf(acc);
    }
}

// -------- routing: per-row min/max over typed columns, atomic-merged --------
__device__ __forceinline__ void route_tile(const float acc[4][4], int b,
                                           int rowb, int colb, int Nb,
                                           int tx, int ty) {
    float nc[4]; int cfg[4], cbg[4];
#pragma unroll
    for (int j = 0; j < 4; j++) {
        int c = colb + 4 * tx + j;
        bool cok = (c < Nb);
        nc[j]  = g_nrm[b * PT + c];
        cfg[j] = cok && g_sfg[b * PT + c];
        cbg[j] = cok && g_sbg[b * PT + c];
    }
#pragma unroll
    for (int i = 0; i < 4; i++) {
        int ri = rowb + 4 * ty + i;
        float nr = g_nrm[b * PT + ri];
        float vFF = BIGV, vBF = -BIGV, vFB = -BIGV, vBB = BIGV;
#pragma unroll
        for (int j = 0; j < 4; j++) {
            float cs = acc[i][j] / fmaxf(nr * nc[j], EPSV);
            if (cfg[j]) { vFF = fminf(vFF, cs); vBF = fmaxf(vBF, cs); }
            if (cbg[j]) { vFB = fmaxf(vFB, cs); vBB = fminf(vBB, cs); }
        }
#pragma unroll
        for (int m = 4; m > 0; m >>= 1) {
            vFF = fminf(vFF, __shfl_xor_sync(0xffffffffu, vFF, m));
            vBF = fmaxf(vBF, __shfl_xor_sync(0xffffffffu, vBF, m));
            vFB = fmaxf(vFB, __shfl_xor_sync(0xffffffffu, vFB, m));
            vBB = fminf(vBB, __shfl_xor_sync(0xffffffffu, vBB, m));
        }
        if (tx == 0 && ri < Nb) {
            if (g_sfg[b * PT + ri]) {
                atomicMin(&g_minff[b * PT + ri], fenc(vFF));
                atomicMax(&g_maxfb[b * PT + ri], fenc(vFB));
            }
            if (g_sbg[b * PT + ri]) {
                atomicMax(&g_maxbf[b * PT + ri], fenc(vBF));
                atomicMin(&g_minbb[b * PT + ri], fenc(vBB));
            }
        }
    }
}

// -------- fused symmetric tiled similarity: 32x32 tiles, 64-thread blocks --------
__global__ void __launch_bounds__(64) k_sim() {
    __shared__ float As[DKC][TS];
    __shared__ float Bs[DKC][TS];
    __shared__ float sT[TS][TS + 1];
    __shared__ int   s_off[BN + 1];

    int tid = threadIdx.x;
    int tx = tid & 7, ty = tid >> 3;

    if (tid == 0) {
        int off = 0;
        for (int b = 0; b < BN; b++) { s_off[b] = off; int t = g_tiles[b]; off += t * (t + 1) / 2; }
        s_off[BN] = off;
    }
    __syncthreads();
    int total = s_off[BN];

    for (int item = blockIdx.x; item < total; item += gridDim.x) {
        int b = 0;
        while (b < BN - 1 && item >= s_off[b + 1]) b++;
        int local = item - s_off[b];
        int tiles = g_tiles[b];
        int rt = 0, rem = local;
        while (rem >= tiles - rt) { rem -= tiles - rt; rt++; }
        int ct = rt + rem;
        int Nb = g_Nb[b];
        int rowb = rt * TS, colb = ct * TS;

        float acc[4][4];
#pragma unroll
        for (int i = 0; i < 4; i++)
#pragma unroll
            for (int j = 0; j < 4; j++) acc[i][j] = 0.f;

        const float* Eb = g_Et + (size_t)b * DD * PT;
#pragma unroll 1
        for (int d0 = 0; d0 < DD; d0 += DKC) {
#pragma unroll
            for (int i = 0; i < 4; i++) {
                int lin = i * 64 + tid;
                int dk = lin >> 3, pq = (lin & 7) * 4;
                const float* rsrc = Eb + (size_t)(d0 + dk) * PT;
                *(float4*)&As[dk][pq] = *(const float4*)(rsrc + rowb + pq);
                *(float4*)&Bs[dk][pq] = *(const float4*)(rsrc + colb + pq);
            }
            __syncthreads();
#pragma unroll
            for (int dk = 0; dk < DKC; dk++) {
                float4 a = *(const float4*)&As[dk][ty * 4];
                float4 c = *(const float4*)&Bs[dk][tx * 4];
                acc[0][0] += a.x * c.x; acc[0][1] += a.x * c.y; acc[0][2] += a.x * c.z; acc[0][3] += a.x * c.w;
                acc[1][0] += a.y * c.x; acc[1][1] += a.y * c.y; acc[1][2] += a.y * c.z; acc[1][3] += a.y * c.w;
                acc[2][0] += a.z * c.x; acc[2][1] += a.z * c.y; acc[2][2] += a.z * c.z; acc[2][3] += a.z * c.w;
                acc[3][0] += a.w * c.x; acc[3][1] += a.w * c.y; acc[3][2] += a.w * c.z; acc[3][3] += a.w * c.w;
            }
            __syncthreads();
        }

        route_tile(acc, b, rowb, colb, Nb, tx, ty);

        if (rt != ct) {
#pragma unroll
            for (int i = 0; i < 4; i++)
#pragma unroll
                for (int j = 0; j < 4; j++)
                    sT[4 * tx + j][4 * ty + i] = acc[i][j];
            __syncthreads();
            float a2[4][4];
#pragma unroll
            for (int i = 0; i < 4; i++)
#pragma unroll
                for (int j = 0; j < 4; j++)
                    a2[i][j] = sT[4 * ty + i][4 * tx + j];
            __syncthreads();
            route_tile(a2, b, colb, rowb, Nb, tx, ty);
        }
    }
}

// -------- per-batch weighted means + fused final (last-block ticket) --------
__global__ void k_batch(float* __restrict__ out) {
    int b = blockIdx.x, tid = threadIdx.x;
    int Nb = g_Nb[b];
    float sff = 0.f, sfb = 0.f, sbb = 0.f, sbf = 0.f;
    for (int p = tid; p < Nb; p += 256) {
        if (g_sfg[b * PT + p]) {
            float wv = (float)g_sw[b * PT + p];
            sff += wv * fmaxf(THSIM - fdec(g_minff[b * PT + p]), 0.f);
            sfb += wv * fmaxf(fdec(g_maxfb[b * PT + p]) - THDIF, 0.f);
        }
        if (g_sbg[b * PT + p]) {
            sbb += fmaxf(THSIM - fdec(g_minbb[b * PT + p]), 0.f);
            sbf += fmaxf(fdec(g_maxbf[b * PT + p]) - THDIF, 0.f);
        }
    }
    __shared__ float r1[256], r2[256], r3[256], r4[256];
    __shared__ int s_last;
    r1[tid] = sff; r2[tid] = sfb; r3[tid] = sbb; r4[tid] = sbf;
    __syncthreads();
    for (int s = 128; s > 0; s >>= 1) {
        if (tid < s) {
            r1[tid] += r1[tid + s]; r2[tid] += r2[tid + s];
            r3[tid] += r3[tid + s]; r4[tid] += r4[tid + s];
        }
        __syncthreads();
    }
    if (tid == 0) {
        int cnt = g_bgcnt[b];
        float denf = fmaxf((float)g_sumw[b], 1.f);
        float denb = fmaxf((float)cnt, 1.f);
        float loss = r1[0] / denf + r2[0] / denf + r3[0] / denb + r4[0] / denb;
        g_perbatch[b] = (cnt > 0) ? loss : 0.f;
        __threadfence();
        int old = atomicAdd(&g_ticket, 1);
        s_last = (old == BN - 1) ? 1 : 0;
    }
    __syncthreads();
    if (s_last && tid == 0) {
        volatile float* pb = g_perbatch;
        float s = 0.f; int c = 0;
        for (int bb = 0; bb < BN; bb++) { s += pb[bb]; if (g_bgcnt[bb] > 0) c++; }
        out[0] = s / fmaxf((float)c, 1.f);
        g_ticket = 0;   // reset for next graph replay
    }
}

extern "C" void kernel_launch(void* const* d_in, const int* in_sizes, int n_in,
                              void* d_out, int out_size) {
    const float* emb    = (const float*)d_in[0];
    const float* cas    = (const float*)d_in[1];
    const int*   click  = (const int*)d_in[2];
    const int*   label  = (const int*)d_in[3];
    const int*   clsnum = (n_in >= 5) ? (const int*)d_in[4] : nullptr;

    k_topk   <<<dim3(CC, BN), 256>>>(cas);
    k_prep   <<<BN, 256>>>(click, label, clsnum);
    k_gatherT<<<dim3(DD / 4, BN), 256>>>(emb);
    k_norm   <<<dim3(PT / 32, BN), 256>>>();
    k_sim    <<<SIM_BLOCKS, 64>>>();
    k_batch  <<<BN, 256>>>((float*)d_out);
}